// round 8
// baseline (speedup 1.0000x reference)
#include <cuda_runtime.h>

// CountVectorizer == per-row bincount over vocab followed by counts @ W + b.
//   out[b, :] = bias + sum_t W[token_ids[b, t], :]   (embedding gather-sum)
//
// Established: timed loop is L2-warm; the binding term is per-CTA completion
// spread, not bandwidth (R6: halving the work quantum 12.4 -> 11.33 us;
// warm L2 delivery 9.3 TB/s vs ~12 TB/s LTS ceiling). This round: quarter-row
// CTAs. grid = 4096, each CTA = (batch row, 128B d-quarter); a warp's gather
// is one contiguous 128B line (4 sectors, zero waste); lane owns one float.
// Disjoint outputs, no atomics, same total gather bytes; LDG-issue floor
// (~5 us chip-wide) stays under the memory time; 4096 CTAs still fit one
// co-resident wave (27.7/SM < 32-block cap).
// (Resubmission of R7 verbatim: that round died on a broker infra flake,
// not the kernel.)

#define CV_BATCH  1024
#define CV_SEQ    200
#define CV_D      128               // d_model
#define CV_QF     32                // floats per quarter row (128 B)
#define CV_WARPS  4

__global__ __launch_bounds__(128)
void count_vectorizer_kernel(const int* __restrict__ token_ids,
                             const float* __restrict__ W,
                             const float* __restrict__ bias,
                             float* __restrict__ out)
{
    __shared__ int   s_ids[CV_SEQ];
    __shared__ float s_acc[CV_WARPS][CV_QF];

    const int b = blockIdx.x >> 2;        // batch row
    const int q = blockIdx.x & 3;         // d-quarter (floats q*32 .. q*32+31)

    // Stage this row's 200 token ids (2 coalesced rounds of 128).
    for (int i = threadIdx.x; i < CV_SEQ; i += 128)
        s_ids[i] = token_ids[b * CV_SEQ + i];
    __syncthreads();

    const int lane = threadIdx.x & 31;    // float within the quarter
    const int w    = threadIdx.x >> 5;    // warp id 0..3 (token stream)
    const int dcol = q * CV_QF + lane;    // float column in the full row

    float acc = 0.f;

    // 50 gathers per warp; each is one contiguous 128B line.
    #pragma unroll 10
    for (int t = w; t < CV_SEQ; t += CV_WARPS)
        acc += __ldg(&W[s_ids[t] * CV_D + dcol]);

    s_acc[w][lane] = acc;
    __syncthreads();

    // Warp 0 folds the 4 partials, adds bias, stores the 128B quarter.
    if (w == 0) {
        float a = s_acc[0][lane] + s_acc[1][lane]
                + s_acc[2][lane] + s_acc[3][lane];
        a += __ldg(&bias[dcol]);
        out[b * CV_D + dcol] = a;
    }
}

extern "C" void kernel_launch(void* const* d_in, const int* in_sizes, int n_in,
                              void* d_out, int out_size)
{
    const int*   token_ids = (const int*)d_in[0];      // [1024, 200] int32
    const float* W         = (const float*)d_in[1];    // [100000, 128] f32
    const float* bias      = (const float*)d_in[2];    // [128] f32
    float*       out       = (float*)d_out;            // [1024, 128] f32

    (void)in_sizes; (void)n_in; (void)out_size;

    count_vectorizer_kernel<<<4 * CV_BATCH, 128>>>(token_ids, W, bias, out);
}